// round 15
// baseline (speedup 1.0000x reference)
#include <cuda_runtime.h>

// Pool_26517128085982: 2x2 mean pool, stride 2, x:(16,64,512,512) f32 -> (16,64,256,256) f32
// FINAL — converged at the DRAM roofline. Compulsory traffic 1.342 GB (1.074 GB read +
// 0.268 GB write, zero reuse, footprint >> L2); achieved ~7.25 TB/s = 90.6% of 8 TB/s
// spec. Residual ~9% is DRAM R/W turnaround + refresh — unreachable from kernel code.
//
// Exploration record (10 benches, all axes closed):
//   R3  flat MLP=4 default:         186.59us, DRAM 91.2%
//   R5  flat MLP=8 .cs load+store:  186.75us, DRAM 89.6%  (.cs loads hurt DRAM read sched)
//   R6  flat MLP=8 default:         186.56us, DRAM 91.5%  <== THIS KERNEL
//   R7  persistent grid-stride:     198.75us, DRAM 85.9%  (loop bubbles starve LDG stream)
//   R8  flat MLP=8 .cg loads:       186.88us, DRAM 91.4%  (L1 bypass neutral)
//   R9  flat MLP=8 block=512:       186.62us, DRAM 90.8%  (neutral)
//   R10 flat MLP=8 .cs stores:      186.94us, DRAM 91.0%  (neutral)
//   R11 re-bench of R6:             186.50us, DRAM 91.0%  (best timed)
//   R12 256-bit v8.f32 accesses:    187.07us, DRAM 91.4%  (neutral; occ 61% suffices)
//   R13 re-bench of R6:             186.88us, DRAM 91.6%  (noise floor ±0.3us)
//   R14 smem write batching:        187.14us, DRAM 91.4%  (neutral; occ 96% changes nothing)
//
// Design: flat one-shot grid (the hardware work distributor keeps the LDG stream dense;
// persistent loops demonstrably starve it), 256 thr/block, each thread produces 2 float4
// outputs at idx and idx+n/2 so every warp-level load/store transaction is fully
// contiguous, 8 front-batched LDG.128 per thread (MLP=8), default cache policy on both
// streams, generic 2x2 kernel weights read from d_in[1].

static constexpr int W_IN    = 512;
static constexpr int W_OUT   = 256;
static constexpr int H_OUT   = 256;
static constexpr int ROW4_IN  = W_IN / 4;          // 128 float4 per input row
static constexpr int ROW4_OUT = W_OUT / 4;         // 64  float4 per output row
static constexpr int IMG4_IN  = W_IN * W_IN / 4;   // 65536 float4 per input image

__device__ __forceinline__ float4 pool4(const float4& a0, const float4& a1,
                                        const float4& b0, const float4& b1,
                                        const float4& k)
{
    float4 o;
    o.x = k.x * a0.x + k.y * a0.y + k.z * b0.x + k.w * b0.y;
    o.y = k.x * a0.z + k.y * a0.w + k.z * b0.z + k.w * b0.w;
    o.z = k.x * a1.x + k.y * a1.y + k.z * b1.x + k.w * b1.y;
    o.w = k.x * a1.z + k.y * a1.w + k.z * b1.z + k.w * b1.w;
    return o;
}

__global__ __launch_bounds__(256) void Pool_26517128085982_kernel(
    const float4* __restrict__ in,
    const float*  __restrict__ kern,   // 4 floats: k00 k01 k10 k11
    float4* __restrict__ out,
    int half_n4)                       // n_out4 / 2
{
    int idx0 = blockIdx.x * blockDim.x + threadIdx.x;
    if (idx0 >= half_n4) return;
    int idx1 = idx0 + half_n4;

    // idx -> (img, oh, oc4): 64 float4 per out row, 256 rows per image
    int oc4a = idx0 & (ROW4_OUT - 1);
    int oha  = (idx0 >> 6) & (H_OUT - 1);
    int imga = idx0 >> 14;
    int basea = imga * IMG4_IN + (oha << 1) * ROW4_IN + (oc4a << 1);

    int oc4b = idx1 & (ROW4_OUT - 1);
    int ohb  = (idx1 >> 6) & (H_OUT - 1);
    int imgb = idx1 >> 14;
    int baseb = imgb * IMG4_IN + (ohb << 1) * ROW4_IN + (oc4b << 1);

    // 8 independent LDG.128 (MLP=8), front-batched, default caching
    float4 a0 = in[basea];
    float4 a1 = in[basea + 1];
    float4 b0 = in[basea + ROW4_IN];
    float4 b1 = in[basea + ROW4_IN + 1];
    float4 c0 = in[baseb];
    float4 c1 = in[baseb + 1];
    float4 d0 = in[baseb + ROW4_IN];
    float4 d1 = in[baseb + ROW4_IN + 1];

    // kernel weights: broadcast load, L1-hit after first warp
    float4 k = *reinterpret_cast<const float4*>(kern);

    out[idx0] = pool4(a0, a1, b0, b1, k);
    out[idx1] = pool4(c0, c1, d0, d1, k);
}

extern "C" void kernel_launch(void* const* d_in, const int* in_sizes, int n_in,
                              void* d_out, int out_size)
{
    const float4* x    = (const float4*)d_in[0];
    const float*  kern = (const float*)d_in[1];
    float4*       out  = (float4*)d_out;

    int n_out4  = out_size / 4;          // 16,777,216 float4
    int half_n4 = n_out4 / 2;            // 8,388,608 threads
    int blocks  = (half_n4 + 255) / 256; // 32,768 blocks
    Pool_26517128085982_kernel<<<blocks, 256>>>(x, kern, out, half_n4);
}

// round 16
// speedup vs baseline: 1.0038x; 1.0038x over previous
#include <cuda_runtime.h>

// Pool_26517128085982: 2x2 mean pool, stride 2, x:(16,64,512,512) f32 -> (16,64,256,256) f32
// FINAL (converged). DRAM-roofline-bound: compulsory 1.342 GB traffic at ~7.25 TB/s
// achieved = 90.6% of 8 TB/s spec. Residual ~9% = DRAM R/W turnaround + refresh,
// outside kernel control. LTS cap is path-independent (LDG ≡ TMA), so no access
// mechanism can beat this.
//
// Exploration record (11 benches; timed noise band ±0.35us established by 4 re-benches):
//   R3  flat MLP=4 default:         186.59us, DRAM 91.2%
//   R5  flat MLP=8 .cs load+store:  186.75us, DRAM 89.6%  (.cs loads hurt DRAM read sched)
//   R6  flat MLP=8 default:         186.56us, DRAM 91.5%  <== THIS KERNEL
//   R7  persistent grid-stride:     198.75us, DRAM 85.9%  (loop bubbles starve LDG stream)
//   R8  flat MLP=8 .cg loads:       186.88us, DRAM 91.4%  (neutral)
//   R9  flat MLP=8 block=512:       186.62us, DRAM 90.8%  (neutral)
//   R10 flat MLP=8 .cs stores:      186.94us, DRAM 91.0%  (neutral)
//   R11 re-bench of R6:             186.50us, DRAM 91.0%  (best timed)
//   R12 256-bit v8.f32 accesses:    187.07us, DRAM 91.4%  (neutral; occ 61% suffices)
//   R13 re-bench of R6:             186.88us, DRAM 91.6%
//   R14 smem write batching:        187.14us, DRAM 91.4%  (neutral; occ 96% changes nothing)
//   R15 re-bench of R6:             187.14us, DRAM 91.5%
//
// Design: flat one-shot grid (hardware distributor keeps the LDG stream dense; persistent
// loops demonstrably starve it), 256 thr/block, each thread produces 2 float4 outputs at
// idx and idx+n/2 so every warp-level load/store transaction is fully contiguous,
// 8 front-batched LDG.128 per thread (MLP=8), default cache policy on both streams,
// generic 2x2 kernel weights read from d_in[1].

static constexpr int W_IN    = 512;
static constexpr int W_OUT   = 256;
static constexpr int H_OUT   = 256;
static constexpr int ROW4_IN  = W_IN / 4;          // 128 float4 per input row
static constexpr int ROW4_OUT = W_OUT / 4;         // 64  float4 per output row
static constexpr int IMG4_IN  = W_IN * W_IN / 4;   // 65536 float4 per input image

__device__ __forceinline__ float4 pool4(const float4& a0, const float4& a1,
                                        const float4& b0, const float4& b1,
                                        const float4& k)
{
    float4 o;
    o.x = k.x * a0.x + k.y * a0.y + k.z * b0.x + k.w * b0.y;
    o.y = k.x * a0.z + k.y * a0.w + k.z * b0.z + k.w * b0.w;
    o.z = k.x * a1.x + k.y * a1.y + k.z * b1.x + k.w * b1.y;
    o.w = k.x * a1.z + k.y * a1.w + k.z * b1.z + k.w * b1.w;
    return o;
}

__global__ __launch_bounds__(256) void Pool_26517128085982_kernel(
    const float4* __restrict__ in,
    const float*  __restrict__ kern,   // 4 floats: k00 k01 k10 k11
    float4* __restrict__ out,
    int half_n4)                       // n_out4 / 2
{
    int idx0 = blockIdx.x * blockDim.x + threadIdx.x;
    if (idx0 >= half_n4) return;
    int idx1 = idx0 + half_n4;

    // idx -> (img, oh, oc4): 64 float4 per out row, 256 rows per image
    int oc4a = idx0 & (ROW4_OUT - 1);
    int oha  = (idx0 >> 6) & (H_OUT - 1);
    int imga = idx0 >> 14;
    int basea = imga * IMG4_IN + (oha << 1) * ROW4_IN + (oc4a << 1);

    int oc4b = idx1 & (ROW4_OUT - 1);
    int ohb  = (idx1 >> 6) & (H_OUT - 1);
    int imgb = idx1 >> 14;
    int baseb = imgb * IMG4_IN + (ohb << 1) * ROW4_IN + (oc4b << 1);

    // 8 independent LDG.128 (MLP=8), front-batched, default caching
    float4 a0 = in[basea];
    float4 a1 = in[basea + 1];
    float4 b0 = in[basea + ROW4_IN];
    float4 b1 = in[basea + ROW4_IN + 1];
    float4 c0 = in[baseb];
    float4 c1 = in[baseb + 1];
    float4 d0 = in[baseb + ROW4_IN];
    float4 d1 = in[baseb + ROW4_IN + 1];

    // kernel weights: broadcast load, L1-hit after first warp
    float4 k = *reinterpret_cast<const float4*>(kern);

    out[idx0] = pool4(a0, a1, b0, b1, k);
    out[idx1] = pool4(c0, c1, d0, d1, k);
}

extern "C" void kernel_launch(void* const* d_in, const int* in_sizes, int n_in,
                              void* d_out, int out_size)
{
    const float4* x    = (const float4*)d_in[0];
    const float*  kern = (const float*)d_in[1];
    float4*       out  = (float4*)d_out;

    int n_out4  = out_size / 4;          // 16,777,216 float4
    int half_n4 = n_out4 / 2;            // 8,388,608 threads
    int blocks  = (half_n4 + 255) / 256; // 32,768 blocks
    Pool_26517128085982_kernel<<<blocks, 256>>>(x, kern, out, half_n4);
}